// round 1
// baseline (speedup 1.0000x reference)
#include <cuda_runtime.h>
#include <cstdint>

#define N_NODES 2048
#define IN_DIM 32
#define LATENT 64

// Scratch (allocation-free rule: __device__ globals)
__device__ float g_zi[N_NODES * LATENT];    // z @ W_e1a
__device__ float g_zjb[N_NODES * LATENT];   // z @ W_e1b + b_e1
__device__ float g_aw2[N_NODES];            // 0.505 * sum_l w_l * zi[i,l]
__device__ float g_cw2[N_NODES];            // 0.505 * sum_l w_l * zjb[j,l] + b_e2
__device__ float g_ws[LATENT];              // 0.495 * w_e2[l]

__device__ __forceinline__ float fabs_bits(float v) {
    return __int_as_float(__float_as_int(v) & 0x7fffffff);
}

// ---------------------------------------------------------------------------
// Kernel 1: per-node precompute.
// z = lrelu(x @ W_ne + b_ne)         [N, L]
// zi = z @ W_e1a                      [N, L]
// zjb = z @ W_e1b + b_e1              [N, L]
// aw2[i] = 0.505 * dot(w_e2, zi[i]); cw2[j] = 0.505 * dot(w_e2, zjb[j]) + b_e2
// One block per node, 64 threads (one per latent).
// ---------------------------------------------------------------------------
__global__ __launch_bounds__(LATENT) void node_precompute_kernel(
    const float* __restrict__ x,
    const float* __restrict__ W_ne, const float* __restrict__ b_ne,
    const float* __restrict__ W_e1a, const float* __restrict__ W_e1b,
    const float* __restrict__ b_e1,
    const float* __restrict__ w_e2, const float* __restrict__ b_e2)
{
    __shared__ float sx[IN_DIM];
    __shared__ float sz[LATENT];
    __shared__ float red1[LATENT];
    __shared__ float red2[LATENT];

    const int n = blockIdx.x;
    const int l = threadIdx.x;

    if (l < IN_DIM) sx[l] = x[n * IN_DIM + l];
    __syncthreads();

    // z_l = lrelu(sum_k x[k]*W_ne[k,l] + b_ne[l])
    float acc = b_ne[l];
#pragma unroll
    for (int k = 0; k < IN_DIM; k++)
        acc = fmaf(sx[k], W_ne[k * LATENT + l], acc);
    float zv = fmaxf(acc, 0.01f * acc);   // leaky_relu(v, 0.01)
    sz[l] = zv;
    __syncthreads();

    float zi_v = 0.0f;
    float zjb_v = b_e1[l];
#pragma unroll
    for (int k = 0; k < LATENT; k++) {
        float zk = sz[k];
        zi_v  = fmaf(zk, W_e1a[k * LATENT + l], zi_v);
        zjb_v = fmaf(zk, W_e1b[k * LATENT + l], zjb_v);
    }
    g_zi[n * LATENT + l]  = zi_v;
    g_zjb[n * LATENT + l] = zjb_v;

    const float w = w_e2[l];
    red1[l] = w * zi_v;
    red2[l] = w * zjb_v;
    __syncthreads();

    if (l < 32) {
        float s1 = red1[l] + red1[l + 32];
        float s2 = red2[l] + red2[l + 32];
#pragma unroll
        for (int off = 16; off > 0; off >>= 1) {
            s1 += __shfl_down_sync(0xffffffffu, s1, off);
            s2 += __shfl_down_sync(0xffffffffu, s2, off);
        }
        if (l == 0) {
            g_aw2[n] = 0.505f * s1;
            g_cw2[n] = 0.505f * s2 + b_e2[0];
        }
    }
    if (n == 0) g_ws[l] = 0.495f * w;
}

// ---------------------------------------------------------------------------
// Kernel 2: pairwise edge probabilities.
// logit(i,j) = aw2[i] + cw2[j] + sum_l ws[l] * |zi[i,l] + zjb[j,l]|
// out = (sigmoid(logit) + 1e-8) * exp(gumbel)
// 64x64 tile per block, 256 threads, 4x4 outputs each.
// ---------------------------------------------------------------------------
__global__ __launch_bounds__(256) void edge_prob_kernel(
    const float* __restrict__ gumbel, float* __restrict__ out)
{
    __shared__ float s_zi[64][68];     // [i][l]  (row start 272B: 16B aligned)
    __shared__ float s_zjbT[64][68];   // [l][j]  transposed
    __shared__ float s_ws[64];
    __shared__ float s_aw[64];
    __shared__ float s_cw[64];

    const int tid = threadIdx.x;
    const int ibase = blockIdx.y * 64;
    const int jbase = blockIdx.x * 64;

#pragma unroll
    for (int t = tid; t < 64 * 64; t += 256) {
        int r = t >> 6, c = t & 63;
        s_zi[r][c]   = g_zi[(ibase + r) * LATENT + c];
        s_zjbT[c][r] = g_zjb[(jbase + r) * LATENT + c];
    }
    if (tid < 64) {
        s_ws[tid] = g_ws[tid];
        s_aw[tid] = g_aw2[ibase + tid];
        s_cw[tid] = g_cw2[jbase + tid];
    }
    __syncthreads();

    const int tx = tid & 15;   // j sub-tile
    const int ty = tid >> 4;   // i sub-tile

    float acc[4][4] = {};

#pragma unroll 4
    for (int lc = 0; lc < 16; lc++) {
        float4 wv = *(const float4*)&s_ws[lc * 4];
        float w[4] = {wv.x, wv.y, wv.z, wv.w};

        float a[4][4];   // [ii][lsub]
#pragma unroll
        for (int ii = 0; ii < 4; ii++) {
            float4 t = *(const float4*)&s_zi[ty * 4 + ii][lc * 4];
            a[ii][0] = t.x; a[ii][1] = t.y; a[ii][2] = t.z; a[ii][3] = t.w;
        }
        float b[4][4];   // [lsub][jj]
#pragma unroll
        for (int u = 0; u < 4; u++) {
            float4 t = *(const float4*)&s_zjbT[lc * 4 + u][tx * 4];
            b[u][0] = t.x; b[u][1] = t.y; b[u][2] = t.z; b[u][3] = t.w;
        }

#pragma unroll
        for (int u = 0; u < 4; u++) {
#pragma unroll
            for (int ii = 0; ii < 4; ii++) {
                float ai = a[ii][u];
#pragma unroll
                for (int jj = 0; jj < 4; jj++) {
                    acc[ii][jj] = fmaf(w[u], fabs_bits(ai + b[u][jj]), acc[ii][jj]);
                }
            }
        }
    }

    // epilogue
#pragma unroll
    for (int ii = 0; ii < 4; ii++) {
        const int i = ibase + ty * 4 + ii;
        const int j0 = jbase + tx * 4;
        const float base_i = s_aw[ty * 4 + ii];
        const size_t off = (size_t)i * N_NODES + j0;
        const float4 gv = *(const float4*)&gumbel[off];
        float g4[4] = {gv.x, gv.y, gv.z, gv.w};
        float4 o;
        float* op = &o.x;
#pragma unroll
        for (int jj = 0; jj < 4; jj++) {
            float logit = acc[ii][jj] + base_i + s_cw[tx * 4 + jj];
            float e = __expf(-logit);
            float p = __fdividef(1.0f, 1.0f + e);
            op[jj] = (p + 1e-8f) * __expf(g4[jj]);
        }
        *(float4*)&out[off] = o;
    }
}

// ---------------------------------------------------------------------------
// Inputs (metadata order):
// 0:x [N,32] 1:in_adj [N,N](unused) 2:gumbel [N,N] 3:W_ne [32,64] 4:b_ne [64]
// 5:W_e1a [64,64] 6:W_e1b [64,64] 7:b_e1 [64] 8:w_e2 [64] 9:b_e2 []
// out: [N,N] float32
// ---------------------------------------------------------------------------
extern "C" void kernel_launch(void* const* d_in, const int* in_sizes, int n_in,
                              void* d_out, int out_size)
{
    const float* x      = (const float*)d_in[0];
    const float* gumbel = (const float*)d_in[2];
    const float* W_ne   = (const float*)d_in[3];
    const float* b_ne   = (const float*)d_in[4];
    const float* W_e1a  = (const float*)d_in[5];
    const float* W_e1b  = (const float*)d_in[6];
    const float* b_e1   = (const float*)d_in[7];
    const float* w_e2   = (const float*)d_in[8];
    const float* b_e2   = (const float*)d_in[9];
    float* out = (float*)d_out;

    node_precompute_kernel<<<N_NODES, LATENT>>>(x, W_ne, b_ne, W_e1a, W_e1b,
                                                b_e1, w_e2, b_e2);
    dim3 grid(N_NODES / 64, N_NODES / 64);
    edge_prob_kernel<<<grid, 256>>>(gumbel, out);
}